// round 14
// baseline (speedup 1.0000x reference)
#include <cuda_runtime.h>
#include <cuda_bf16.h>
#include <math.h>
#include <stdint.h>

#define B_  32
#define TI_ 4096
#define D_  512
#define M_TOTAL (B_ * TI_)   /* 131072 */
#define NCHUNK 4             /* 512 / 128 n-chunks */
#define TSPLIT 32

// ---------------------------------------------------------------------------
// Device scratch (allocation-free; every element written before read each call)
// ---------------------------------------------------------------------------
__device__ float g_qk[B_ * D_];
__device__ float g_scores_part[NCHUNK * M_TOTAL];
__device__ float g_attn[M_TOTAL];
__device__ float g_mix_part[TSPLIT * B_ * D_];
__device__ uint32_t g_WkT[D_ * D_];   // Wk tf32-rounded (raw b32)

// SW128 swizzle (Swizzle<3,4,3>) on tile-relative byte offsets
#define SWZ(off) ((off) ^ (((off) >> 3) & 0x70))

__device__ __forceinline__ uint32_t smem_u32(const void* p) {
    uint32_t a;
    asm("{ .reg .u64 t; cvta.to.shared.u64 t, %1; cvt.u32.u64 %0, t; }" : "=r"(a) : "l"(p));
    return a;
}
// cvt.rna.tf32.f32 writes a .b32 destination (raw tf32 bit pattern)
__device__ __forceinline__ uint32_t to_tf32(float x) {
    uint32_t r;
    asm("cvt.rna.tf32.f32 %0, %1;" : "=r"(r) : "f"(x));
    return r;
}
__device__ __forceinline__ void ldsm4(uint32_t* r, uint32_t addr) {
    asm volatile("ldmatrix.sync.aligned.m8n8.x4.shared.b16 {%0,%1,%2,%3}, [%4];"
                 : "=r"(r[0]), "=r"(r[1]), "=r"(r[2]), "=r"(r[3]) : "r"(addr));
}
__device__ __forceinline__ void mma_tf32(float* c, const uint32_t* a, uint32_t b0, uint32_t b1) {
    asm volatile("mma.sync.aligned.m16n8k8.row.col.f32.tf32.tf32.f32 "
                 "{%0,%1,%2,%3}, {%4,%5,%6,%7}, {%8,%9}, {%0,%1,%2,%3};"
                 : "+f"(c[0]), "+f"(c[1]), "+f"(c[2]), "+f"(c[3])
                 : "r"(a[0]), "r"(a[1]), "r"(a[2]), "r"(a[3]), "r"(b0), "r"(b1));
}
__device__ __forceinline__ void cp_async16(uint32_t dst, const void* src) {
    asm volatile("cp.async.cg.shared.global [%0], [%1], 16;" :: "r"(dst), "l"(src));
}
#define CP_COMMIT() asm volatile("cp.async.commit_group;" ::: "memory")
#define CP_WAIT0()  asm volatile("cp.async.wait_group 0;" ::: "memory")
#define CP_WAIT1()  asm volatile("cp.async.wait_group 1;" ::: "memory")

__device__ __forceinline__ float fast_tanhf(float x) {
    // tanh(x) = 1 - 2/(exp(2x)+1); exact at saturation
    return 1.0f - 2.0f / (__expf(2.0f * x) + 1.0f);
}

// ---------------------------------------------------------------------------
// SMEM layout for k_scores_mma: 3 stages x (A 16KB + B 16KB) = 96KB + tail.
// Rows = 128B, SW128-swizzled. 2 CTAs/SM (196KB < 228KB).
// ---------------------------------------------------------------------------
#define STG_SZ  32768
#define OFF_QK  98304          /* 128 floats */
#define OFF_WV  98816          /* 128 floats */
#define OFF_RED 99328          /* 2 x 128 floats */
#define SMEM_SC 100352

// ---------------------------------------------------------------------------
// k_prep_query (fused): blocks 0..255 convert Wk -> tf32; blocks 256..287
// compute g_qk[b][d] = output[b] . Wq[d] + bq[d] + bk[d] (256 threads).
// ---------------------------------------------------------------------------
__global__ void k_prep_query(const float* __restrict__ Wk,
                             const float* __restrict__ outp,
                             const float* __restrict__ Wq,
                             const float* __restrict__ bq,
                             const float* __restrict__ bk) {
    __shared__ float so[D_];
    int tid = threadIdx.x;                           // 256 threads
    if (blockIdx.x < 256) {
        int idx = blockIdx.x * 256 + tid;            // 65536 float4 jobs
        float4 v = ((const float4*)Wk)[idx];
        uint4 o;
        o.x = to_tf32(v.x); o.y = to_tf32(v.y); o.z = to_tf32(v.z); o.w = to_tf32(v.w);
        ((uint4*)g_WkT)[idx] = o;
        return;
    }
    int b = blockIdx.x - 256;
    so[tid]       = outp[b * D_ + tid];
    so[tid + 256] = outp[b * D_ + tid + 256];
    __syncthreads();
    int warp = tid >> 5, lane = tid & 31;            // 8 warps
    for (int d = warp; d < D_; d += 8) {
        const float* w = Wq + (size_t)d * D_;
        float s = 0.f;
#pragma unroll 4
        for (int j = lane; j < D_; j += 32) s += so[j] * w[j];
#pragma unroll
        for (int o = 16; o > 0; o >>= 1) s += __shfl_down_sync(0xffffffffu, s, o);
        if (lane == 0) g_qk[b * D_ + d] = s + bq[d] + bk[d];
    }
}

// ---------------------------------------------------------------------------
// cp.async stage fills (4 x 16B per thread each; no registers, no cvt)
// A comes straight from the fp32 ctx input (tf32 HW truncates mantissa).
// ---------------------------------------------------------------------------
__device__ __forceinline__ void cpA(const float* __restrict__ ctx,
                                    int m0, int kc, uint32_t smA, int tid) {
    const int col0 = kc * 32;
#pragma unroll
    for (int it = 0; it < 4; ++it) {
        int j = tid + it * 256;
        int row = j >> 3, seg = j & 7;
        const float* src = ctx + (size_t)(m0 + row) * D_ + col0 + seg * 4;
        cp_async16(smA + SWZ((uint32_t)(row * 128 + seg * 16)), src);
    }
}
__device__ __forceinline__ void cpB(int n0, int kc, uint32_t smB, int tid) {
    const int col0 = kc * 32;
#pragma unroll
    for (int it = 0; it < 4; ++it) {
        int j = tid + it * 256;
        int row = j >> 3, seg = j & 7;
        const uint32_t* src = g_WkT + (size_t)(n0 + row) * D_ + col0 + seg * 4;
        cp_async16(smB + SWZ((uint32_t)(row * 128 + seg * 16)), src);
    }
}

// ---------------------------------------------------------------------------
// k_scores_mma (dominant): tf32 mma.sync GEMM, 3-stage cp.async ring,
// tanh/Wv epilogue. Grid (NCHUNK, 1024), 256 threads (8 warps, 32m x 64n).
// UNCHANGED from R13-passing version.
// ---------------------------------------------------------------------------
__global__ void __launch_bounds__(256, 2)
k_scores_mma(const float* __restrict__ ctx, const float* __restrict__ Wv) {
    extern __shared__ char smem[];
    const int tid  = threadIdx.x;
    const int lane = tid & 31, wid = tid >> 5;
    const int wm = wid >> 1, wn = wid & 1;
    const int n0 = blockIdx.x * 128;
    const int m0 = blockIdx.y * 128;
    const int b  = m0 >> 12;

    float* sQk  = (float*)(smem + OFF_QK);
    float* sWv  = (float*)(smem + OFF_WV);
    float* sred = (float*)(smem + OFF_RED);
    if (tid < 128) { sQk[tid] = g_qk[b * D_ + n0 + tid]; sWv[tid] = Wv[n0 + tid]; }

    // per-lane ldmatrix address constants (tf32 = b16 pairs; same tile scheme)
    const int q = lane >> 3, r = lane & 7;
    const uint32_t rowA  = wm * 32 + ((q & 1) << 3) + r;
    const uint32_t segA  = (q >> 1) << 4;
    const uint32_t xorA  = (rowA & 7) << 4;
    const uint32_t baseA = rowA << 7;
    const uint32_t rowB  = wn * 64 + ((q >> 1) << 3) + r;
    const uint32_t segB  = (q & 1) << 4;
    const uint32_t xorB  = (rowB & 7) << 4;
    const uint32_t baseB = rowB << 7;

    const uint32_t sb = smem_u32(smem);

    float acc[2][8][4];
#pragma unroll
    for (int mi = 0; mi < 2; ++mi)
#pragma unroll
        for (int nt = 0; nt < 8; ++nt)
#pragma unroll
            for (int c = 0; c < 4; ++c) acc[mi][nt][c] = 0.f;

    // Prologue: stages 0 and 1 in flight
    cpA(ctx, m0, 0, sb + 0 * STG_SZ, tid); cpB(n0, 0, sb + 0 * STG_SZ + 16384, tid); CP_COMMIT();
    cpA(ctx, m0, 1, sb + 1 * STG_SZ, tid); cpB(n0, 1, sb + 1 * STG_SZ + 16384, tid); CP_COMMIT();

    int stg = 0;
    for (int kc = 0; kc < 16; ++kc) {
        if (kc < 14) CP_WAIT1(); else CP_WAIT0();   // stage kc resident
        __syncthreads();                            // all warps done with stage kc-1's buffer

        if (kc + 2 < 16) {                          // refill buffer (kc+2)%3 (held kc-1)
            int nstg = stg + 2; if (nstg >= 3) nstg -= 3;
            uint32_t base = sb + nstg * STG_SZ;
            cpA(ctx, m0, kc + 2, base, tid);
            cpB(n0, kc + 2, base + 16384, tid);
            CP_COMMIT();
        }

        const uint32_t sAs = sb + stg * STG_SZ;
        const uint32_t sBs = sAs + 16384;
#pragma unroll
        for (int ks = 0; ks < 4; ++ks) {            // 4 k8-steps per 32-col chunk
            uint32_t a[2][4];
            uint32_t bb[4][4];
#pragma unroll
            for (int mi = 0; mi < 2; ++mi)
                ldsm4(a[mi], sAs + baseA + mi * 2048 +
                      (((uint32_t)(ks * 32) + segA) ^ xorA));
#pragma unroll
            for (int p = 0; p < 4; ++p)
                ldsm4(bb[p], sBs + baseB + p * 2048 +
                      (((uint32_t)(ks * 32) + segB) ^ xorB));
#pragma unroll
            for (int mi = 0; mi < 2; ++mi)
#pragma unroll
                for (int np = 0; np < 8; ++np) {
                    const uint32_t* bp = bb[np >> 1] + ((np & 1) ? 2 : 0);
                    mma_tf32(acc[mi][np], a[mi], bp[0], bp[1]);
                }
        }
        if (++stg == 3) stg = 0;
    }

    // Epilogue: score_part[row] = sum_n Wv[n] * tanh(acc + qk[n]) over 128 cols
#pragma unroll
    for (int mi = 0; mi < 2; ++mi) {
#pragma unroll
        for (int part = 0; part < 2; ++part) {
            float s = 0.f;
#pragma unroll
            for (int nt = 0; nt < 8; ++nt) {
                int col = wn * 64 + nt * 8 + 2 * (lane & 3);
                s += sWv[col]     * fast_tanhf(acc[mi][nt][part * 2]     + sQk[col]);
                s += sWv[col + 1] * fast_tanhf(acc[mi][nt][part * 2 + 1] + sQk[col + 1]);
            }
            s += __shfl_xor_sync(0xffffffffu, s, 1);
            s += __shfl_xor_sync(0xffffffffu, s, 2);
            if ((lane & 3) == 0)
                sred[wn * 128 + wm * 32 + mi * 16 + part * 8 + (lane >> 2)] = s;
        }
    }
    __syncthreads();
    if (tid < 128)
        g_scores_part[blockIdx.x * M_TOTAL + m0 + tid] = sred[tid] + sred[128 + tid];
}

// ---------------------------------------------------------------------------
// k_softmax: float4-vectorized partial reduce, softmax over TI per batch
// ---------------------------------------------------------------------------
__global__ void k_softmax(float* __restrict__ attn_out) {
    __shared__ float s[TI_];
    __shared__ float red[512];
    int b = blockIdx.x, tid = threadIdx.x;   // 512 threads

    for (int t4 = tid; t4 < TI_ / 4; t4 += 512) {
        float4 v = ((const float4*)&g_scores_part[b * TI_])[t4];
#pragma unroll
        for (int p = 1; p < NCHUNK; ++p) {
            float4 w = ((const float4*)&g_scores_part[p * M_TOTAL + b * TI_])[t4];
            v.x += w.x; v.y += w.y; v.z += w.z; v.w += w.w;
        }
        ((float4*)s)[t4] = v;
    }
    __syncthreads();

    float m = -1e30f;
    for (int t = tid; t < TI_; t += 512) m = fmaxf(m, s[t]);
    red[tid] = m; __syncthreads();
    for (int o = 256; o > 0; o >>= 1) {
        if (tid < o) red[tid] = fmaxf(red[tid], red[tid + o]);
        __syncthreads();
    }
    m = red[0]; __syncthreads();

    float sum = 0.f;
    for (int t = tid; t < TI_; t += 512) { float e = expf(s[t] - m); s[t] = e; sum += e; }
    red[tid] = sum; __syncthreads();
    for (int o = 256; o > 0; o >>= 1) {
        if (tid < o) red[tid] += red[tid + o];
        __syncthreads();
    }
    float inv = 1.f / red[0];

    for (int t = tid; t < TI_; t += 512) {
        float av = s[t] * inv;
        g_attn[b * TI_ + t] = av;
        if (attn_out) attn_out[b * TI_ + t] = av;
    }
}

// ---------------------------------------------------------------------------
// k_mix: 128-token splits, 256 threads (2 token-halves x 128 float4 cols)
// ---------------------------------------------------------------------------
__global__ void k_mix(const float* __restrict__ ctx) {
    __shared__ float sa[128];
    __shared__ float4 sred[128];
    int b = blockIdx.y, t0 = blockIdx.x * 128, tid = threadIdx.x;  // 256 threads
    if (tid < 128) sa[tid] = g_attn[b * TI_ + t0 + tid];
    __syncthreads();
    int col = tid & 127, half = tid >> 7;
    const float4* cp = (const float4*)(ctx + ((size_t)b * TI_ + t0 + half * 64) * D_);
    float4 acc = make_float4(0.f, 0.f, 0.f, 0.f);
#pragma unroll 8
    for (int t = 0; t < 64; ++t) {
        float av = sa[half * 64 + t];
        float4 v = cp[(size_t)t * 128 + col];
        acc.x += av * v.x; acc.y += av * v.y; acc.z += av * v.z; acc.w += av * v.w;
    }
    if (half == 1) sred[col] = acc;
    __syncthreads();
    if (half == 0) {
        float4 o = sred[col];
        acc.x += o.x; acc.y += o.y; acc.z += o.z; acc.w += o.w;
        ((float4*)&g_mix_part[(blockIdx.x * B_ + b) * D_])[col] = acc;
    }
}

// ---------------------------------------------------------------------------
// k_out: reduce mix partials, concat with output, Wo projection + tanh
// ---------------------------------------------------------------------------
__global__ void k_out(const float* __restrict__ outp, const float* __restrict__ Wo,
                      const float* __restrict__ bo, float* __restrict__ out_out,
                      float* __restrict__ mix_out) {
    __shared__ float comb[2 * D_];
    int b = blockIdx.x, tid = threadIdx.x;   // 512 threads
    float mv = 0.f;
#pragma unroll
    for (int sp = 0; sp < TSPLIT; ++sp) mv += g_mix_part[(sp * B_ + b) * D_ + tid];
    comb[tid] = mv;
    if (mix_out) mix_out[b * D_ + tid] = mv;
    comb[D_ + tid] = outp[b * D_ + tid];
    __syncthreads();

    int warp = tid >> 5, lane = tid & 31;
    for (int d = warp; d < D_; d += 16) {
        const float* w = Wo + (size_t)d * (2 * D_);
        float s = 0.f;
#pragma unroll 4
        for (int j = lane; j < 2 * D_; j += 32) s += comb[j] * w[j];
#pragma unroll
        for (int o = 16; o > 0; o >>= 1) s += __shfl_down_sync(0xffffffffu, s, o);
        if (lane == 0) out_out[b * D_ + d] = tanhf(s + bo[d]);
    }
}

// ---------------------------------------------------------------------------
extern "C" void kernel_launch(void* const* d_in, const int* in_sizes, int n_in,
                              void* d_out, int out_size) {
    (void)in_sizes; (void)n_in;
    const float* outp = (const float*)d_in[0];
    const float* ctx  = (const float*)d_in[1];
    const float* Wq   = (const float*)d_in[2];
    const float* bq   = (const float*)d_in[3];
    const float* Wk   = (const float*)d_in[4];
    const float* bk   = (const float*)d_in[5];
    const float* Wv   = (const float*)d_in[6];
    /* d_in[7] = bv: cancels in softmax */
    const float* Wo   = (const float*)d_in[8];
    const float* bo   = (const float*)d_in[9];

    float* o        = (float*)d_out;
    float* out_out  = o;
    float* attn_out = nullptr;
    float* mix_out  = nullptr;
    if (out_size >= B_ * D_ + B_ * TI_ + B_ * D_) {
        attn_out = o + B_ * D_;
        mix_out  = o + B_ * D_ + B_ * TI_;
    }

    cudaFuncSetAttribute(k_scores_mma, cudaFuncAttributeMaxDynamicSharedMemorySize, SMEM_SC);

    k_prep_query<<<256 + B_, 256>>>(Wk, outp, Wq, bq, bk);
    k_scores_mma<<<dim3(NCHUNK, M_TOTAL / 128), 256, SMEM_SC>>>(ctx, Wv);
    k_softmax<<<B_, 512>>>(attn_out);
    k_mix<<<dim3(TSPLIT, B_), 256>>>(ctx);
    k_out<<<B_, 512>>>(outp, Wo, bo, out_out, mix_out);
}

// round 15
// speedup vs baseline: 1.1252x; 1.1252x over previous
#include <cuda_runtime.h>
#include <cuda_bf16.h>
#include <math.h>
#include <stdint.h>

#define B_  32
#define TI_ 4096
#define D_  512
#define M_TOTAL (B_ * TI_)   /* 131072 */
#define NCHUNK 4             /* 512 / 128 n-chunks */
#define TSPLIT 32

// ---------------------------------------------------------------------------
// Device scratch (allocation-free; every element written before read each call)
// ---------------------------------------------------------------------------
__device__ float g_qk[B_ * D_];
__device__ float g_scores_part[NCHUNK * M_TOTAL];
__device__ float g_attn[M_TOTAL];
__device__ float g_mix_part[TSPLIT * B_ * D_];
__device__ uint32_t g_WkT[D_ * D_];   // Wk tf32-rounded (raw b32)

// SW128 swizzle (Swizzle<3,4,3>) on tile-relative byte offsets
#define SWZ(off) ((off) ^ (((off) >> 3) & 0x70))

__device__ __forceinline__ uint32_t smem_u32(const void* p) {
    uint32_t a;
    asm("{ .reg .u64 t; cvta.to.shared.u64 t, %1; cvt.u32.u64 %0, t; }" : "=r"(a) : "l"(p));
    return a;
}
// cvt.rna.tf32.f32 writes a .b32 destination (raw tf32 bit pattern)
__device__ __forceinline__ uint32_t to_tf32(float x) {
    uint32_t r;
    asm("cvt.rna.tf32.f32 %0, %1;" : "=r"(r) : "f"(x));
    return r;
}
__device__ __forceinline__ void ldsm4(uint32_t* r, uint32_t addr) {
    asm volatile("ldmatrix.sync.aligned.m8n8.x4.shared.b16 {%0,%1,%2,%3}, [%4];"
                 : "=r"(r[0]), "=r"(r[1]), "=r"(r[2]), "=r"(r[3]) : "r"(addr));
}
__device__ __forceinline__ void mma_tf32(float* c, const uint32_t* a, uint32_t b0, uint32_t b1) {
    asm volatile("mma.sync.aligned.m16n8k8.row.col.f32.tf32.tf32.f32 "
                 "{%0,%1,%2,%3}, {%4,%5,%6,%7}, {%8,%9}, {%0,%1,%2,%3};"
                 : "+f"(c[0]), "+f"(c[1]), "+f"(c[2]), "+f"(c[3])
                 : "r"(a[0]), "r"(a[1]), "r"(a[2]), "r"(a[3]), "r"(b0), "r"(b1));
}
__device__ __forceinline__ void cp_async16(uint32_t dst, const void* src) {
    asm volatile("cp.async.cg.shared.global [%0], [%1], 16;" :: "r"(dst), "l"(src));
}
#define CP_COMMIT() asm volatile("cp.async.commit_group;" ::: "memory")
#define CP_WAIT0()  asm volatile("cp.async.wait_group 0;" ::: "memory")
#define CP_WAIT1()  asm volatile("cp.async.wait_group 1;" ::: "memory")

__device__ __forceinline__ float fast_tanhf(float x) {
    // tanh(x) = 1 - 2/(exp(2x)+1); exact at saturation
    return 1.0f - 2.0f / (__expf(2.0f * x) + 1.0f);
}

// ---------------------------------------------------------------------------
// SMEM layout for k_scores_mma: 3 stages x (A 16KB + B 16KB) = 96KB + tail.
// Rows = 128B, SW128-swizzled. 2 CTAs/SM (196KB < 228KB).
// ---------------------------------------------------------------------------
#define STG_SZ  32768
#define OFF_QK  98304          /* 128 floats */
#define OFF_WV  98816          /* 128 floats */
#define OFF_RED 99328          /* 2 x 128 floats */
#define SMEM_SC 100352

// ---------------------------------------------------------------------------
// k_prep: Wk fp32 -> tf32-rounded raw b32 (1 MB). (R13 version)
// ---------------------------------------------------------------------------
__global__ void k_prep(const float* __restrict__ Wk) {
    int idx = blockIdx.x * 256 + threadIdx.x;       // 65536 float4 jobs
    float4 v = ((const float4*)Wk)[idx];
    uint4 o;
    o.x = to_tf32(v.x); o.y = to_tf32(v.y); o.z = to_tf32(v.z); o.w = to_tf32(v.w);
    ((uint4*)g_WkT)[idx] = o;
}

// ---------------------------------------------------------------------------
// k_query: g_qk[b][d] = output[b] . Wq[d] + bq[d] + bk[d]  (R13 version)
// ---------------------------------------------------------------------------
__global__ void k_query(const float* __restrict__ outp, const float* __restrict__ Wq,
                        const float* __restrict__ bq, const float* __restrict__ bk) {
    __shared__ float so[D_];
    int b = blockIdx.x, tid = threadIdx.x;          // 512 threads
    so[tid] = outp[b * D_ + tid];
    __syncthreads();
    int warp = tid >> 5, lane = tid & 31;
    for (int d = warp; d < D_; d += 16) {
        const float* w = Wq + (size_t)d * D_;
        float s = 0.f;
#pragma unroll 4
        for (int j = lane; j < D_; j += 32) s += so[j] * w[j];
#pragma unroll
        for (int o = 16; o > 0; o >>= 1) s += __shfl_down_sync(0xffffffffu, s, o);
        if (lane == 0) g_qk[b * D_ + d] = s + bq[d] + bk[d];
    }
}

// ---------------------------------------------------------------------------
// cp.async stage fills (4 x 16B per thread each; no registers, no cvt)
// A comes straight from the fp32 ctx input (tf32 HW truncates mantissa).
// ---------------------------------------------------------------------------
__device__ __forceinline__ void cpA(const float* __restrict__ ctx,
                                    int m0, int kc, uint32_t smA, int tid) {
    const int col0 = kc * 32;
#pragma unroll
    for (int it = 0; it < 4; ++it) {
        int j = tid + it * 256;
        int row = j >> 3, seg = j & 7;
        const float* src = ctx + (size_t)(m0 + row) * D_ + col0 + seg * 4;
        cp_async16(smA + SWZ((uint32_t)(row * 128 + seg * 16)), src);
    }
}
__device__ __forceinline__ void cpB(int n0, int kc, uint32_t smB, int tid) {
    const int col0 = kc * 32;
#pragma unroll
    for (int it = 0; it < 4; ++it) {
        int j = tid + it * 256;
        int row = j >> 3, seg = j & 7;
        const uint32_t* src = g_WkT + (size_t)(n0 + row) * D_ + col0 + seg * 4;
        cp_async16(smB + SWZ((uint32_t)(row * 128 + seg * 16)), src);
    }
}

// ---------------------------------------------------------------------------
// k_scores_mma (dominant): tf32 mma.sync GEMM, 3-stage cp.async ring,
// tanh/Wv epilogue. Grid (NCHUNK, 1024), 256 threads (8 warps, 32m x 64n).
// UNCHANGED (stable at ~367us across 3 runs).
// ---------------------------------------------------------------------------
__global__ void __launch_bounds__(256, 2)
k_scores_mma(const float* __restrict__ ctx, const float* __restrict__ Wv) {
    extern __shared__ char smem[];
    const int tid  = threadIdx.x;
    const int lane = tid & 31, wid = tid >> 5;
    const int wm = wid >> 1, wn = wid & 1;
    const int n0 = blockIdx.x * 128;
    const int m0 = blockIdx.y * 128;
    const int b  = m0 >> 12;

    float* sQk  = (float*)(smem + OFF_QK);
    float* sWv  = (float*)(smem + OFF_WV);
    float* sred = (float*)(smem + OFF_RED);
    if (tid < 128) { sQk[tid] = g_qk[b * D_ + n0 + tid]; sWv[tid] = Wv[n0 + tid]; }

    // per-lane ldmatrix address constants (tf32 = b16 pairs; same tile scheme)
    const int q = lane >> 3, r = lane & 7;
    const uint32_t rowA  = wm * 32 + ((q & 1) << 3) + r;
    const uint32_t segA  = (q >> 1) << 4;
    const uint32_t xorA  = (rowA & 7) << 4;
    const uint32_t baseA = rowA << 7;
    const uint32_t rowB  = wn * 64 + ((q >> 1) << 3) + r;
    const uint32_t segB  = (q & 1) << 4;
    const uint32_t xorB  = (rowB & 7) << 4;
    const uint32_t baseB = rowB << 7;

    const uint32_t sb = smem_u32(smem);

    float acc[2][8][4];
#pragma unroll
    for (int mi = 0; mi < 2; ++mi)
#pragma unroll
        for (int nt = 0; nt < 8; ++nt)
#pragma unroll
            for (int c = 0; c < 4; ++c) acc[mi][nt][c] = 0.f;

    // Prologue: stages 0 and 1 in flight
    cpA(ctx, m0, 0, sb + 0 * STG_SZ, tid); cpB(n0, 0, sb + 0 * STG_SZ + 16384, tid); CP_COMMIT();
    cpA(ctx, m0, 1, sb + 1 * STG_SZ, tid); cpB(n0, 1, sb + 1 * STG_SZ + 16384, tid); CP_COMMIT();

    int stg = 0;
    for (int kc = 0; kc < 16; ++kc) {
        if (kc < 14) CP_WAIT1(); else CP_WAIT0();   // stage kc resident
        __syncthreads();                            // all warps done with stage kc-1's buffer

        if (kc + 2 < 16) {                          // refill buffer (kc+2)%3 (held kc-1)
            int nstg = stg + 2; if (nstg >= 3) nstg -= 3;
            uint32_t base = sb + nstg * STG_SZ;
            cpA(ctx, m0, kc + 2, base, tid);
            cpB(n0, kc + 2, base + 16384, tid);
            CP_COMMIT();
        }

        const uint32_t sAs = sb + stg * STG_SZ;
        const uint32_t sBs = sAs + 16384;
#pragma unroll
        for (int ks = 0; ks < 4; ++ks) {            // 4 k8-steps per 32-col chunk
            uint32_t a[2][4];
            uint32_t bb[4][4];
#pragma unroll
            for (int mi = 0; mi < 2; ++mi)
                ldsm4(a[mi], sAs + baseA + mi * 2048 +
                      (((uint32_t)(ks * 32) + segA) ^ xorA));
#pragma unroll
            for (int p = 0; p < 4; ++p)
                ldsm4(bb[p], sBs + baseB + p * 2048 +
                      (((uint32_t)(ks * 32) + segB) ^ xorB));
#pragma unroll
            for (int mi = 0; mi < 2; ++mi)
#pragma unroll
                for (int np = 0; np < 8; ++np) {
                    const uint32_t* bp = bb[np >> 1] + ((np & 1) ? 2 : 0);
                    mma_tf32(acc[mi][np], a[mi], bp[0], bp[1]);
                }
        }
        if (++stg == 3) stg = 0;
    }

    // Epilogue: score_part[row] = sum_n Wv[n] * tanh(acc + qk[n]) over 128 cols
#pragma unroll
    for (int mi = 0; mi < 2; ++mi) {
#pragma unroll
        for (int part = 0; part < 2; ++part) {
            float s = 0.f;
#pragma unroll
            for (int nt = 0; nt < 8; ++nt) {
                int col = wn * 64 + nt * 8 + 2 * (lane & 3);
                s += sWv[col]     * fast_tanhf(acc[mi][nt][part * 2]     + sQk[col]);
                s += sWv[col + 1] * fast_tanhf(acc[mi][nt][part * 2 + 1] + sQk[col + 1]);
            }
            s += __shfl_xor_sync(0xffffffffu, s, 1);
            s += __shfl_xor_sync(0xffffffffu, s, 2);
            if ((lane & 3) == 0)
                sred[wn * 128 + wm * 32 + mi * 16 + part * 8 + (lane >> 2)] = s;
        }
    }
    __syncthreads();
    if (tid < 128)
        g_scores_part[blockIdx.x * M_TOTAL + m0 + tid] = sred[tid] + sred[128 + tid];
}

// ---------------------------------------------------------------------------
// k_softmax: sum n-chunk partials, softmax over TI per batch (R13 version)
// ---------------------------------------------------------------------------
__global__ void k_softmax(float* __restrict__ attn_out) {
    __shared__ float s[TI_];
    __shared__ float red[512];
    int b = blockIdx.x, tid = threadIdx.x;   // 512 threads

    for (int t = tid; t < TI_; t += 512) {
        float v = 0.f;
#pragma unroll
        for (int p = 0; p < NCHUNK; ++p) v += g_scores_part[p * M_TOTAL + b * TI_ + t];
        s[t] = v;
    }
    __syncthreads();

    float m = -1e30f;
    for (int t = tid; t < TI_; t += 512) m = fmaxf(m, s[t]);
    red[tid] = m; __syncthreads();
    for (int o = 256; o > 0; o >>= 1) {
        if (tid < o) red[tid] = fmaxf(red[tid], red[tid + o]);
        __syncthreads();
    }
    m = red[0]; __syncthreads();

    float sum = 0.f;
    for (int t = tid; t < TI_; t += 512) { float e = expf(s[t] - m); s[t] = e; sum += e; }
    red[tid] = sum; __syncthreads();
    for (int o = 256; o > 0; o >>= 1) {
        if (tid < o) red[tid] += red[tid + o];
        __syncthreads();
    }
    float inv = 1.f / red[0];

    for (int t = tid; t < TI_; t += 512) {
        float av = s[t] * inv;
        g_attn[b * TI_ + t] = av;
        if (attn_out) attn_out[b * TI_ + t] = av;
    }
}

// ---------------------------------------------------------------------------
// k_mix: 128-token splits, 256 threads (R14 version — measured 49.0us, 69.6% HBM)
// ---------------------------------------------------------------------------
__global__ void k_mix(const float* __restrict__ ctx) {
    __shared__ float sa[128];
    __shared__ float4 sred[128];
    int b = blockIdx.y, t0 = blockIdx.x * 128, tid = threadIdx.x;  // 256 threads
    if (tid < 128) sa[tid] = g_attn[b * TI_ + t0 + tid];
    __syncthreads();
    int col = tid & 127, half = tid >> 7;
    const float4* cp = (const float4*)(ctx + ((size_t)b * TI_ + t0 + half * 64) * D_);
    float4 acc = make_float4(0.f, 0.f, 0.f, 0.f);
#pragma unroll 8
    for (int t = 0; t < 64; ++t) {
        float av = sa[half * 64 + t];
        float4 v = cp[(size_t)t * 128 + col];
        acc.x += av * v.x; acc.y += av * v.y; acc.z += av * v.z; acc.w += av * v.w;
    }
    if (half == 1) sred[col] = acc;
    __syncthreads();
    if (half == 0) {
        float4 o = sred[col];
        acc.x += o.x; acc.y += o.y; acc.z += o.z; acc.w += o.w;
        ((float4*)&g_mix_part[(blockIdx.x * B_ + b) * D_])[col] = acc;
    }
}

// ---------------------------------------------------------------------------
// k_out: reduce mix partials, concat with output, Wo projection + tanh
// ---------------------------------------------------------------------------
__global__ void k_out(const float* __restrict__ outp, const float* __restrict__ Wo,
                      const float* __restrict__ bo, float* __restrict__ out_out,
                      float* __restrict__ mix_out) {
    __shared__ float comb[2 * D_];
    int b = blockIdx.x, tid = threadIdx.x;   // 512 threads
    float mv = 0.f;
#pragma unroll
    for (int sp = 0; sp < TSPLIT; ++sp) mv += g_mix_part[(sp * B_ + b) * D_ + tid];
    comb[tid] = mv;
    if (mix_out) mix_out[b * D_ + tid] = mv;
    comb[D_ + tid] = outp[b * D_ + tid];
    __syncthreads();

    int warp = tid >> 5, lane = tid & 31;
    for (int d = warp; d < D_; d += 16) {
        const float* w = Wo + (size_t)d * (2 * D_);
        float s = 0.f;
#pragma unroll 4
        for (int j = lane; j < 2 * D_; j += 32) s += comb[j] * w[j];
#pragma unroll
        for (int o = 16; o > 0; o >>= 1) s += __shfl_down_sync(0xffffffffu, s, o);
        if (lane == 0) out_out[b * D_ + d] = tanhf(s + bo[d]);
    }
}

// ---------------------------------------------------------------------------
extern "C" void kernel_launch(void* const* d_in, const int* in_sizes, int n_in,
                              void* d_out, int out_size) {
    (void)in_sizes; (void)n_in;
    const float* outp = (const float*)d_in[0];
    const float* ctx  = (const float*)d_in[1];
    const float* Wq   = (const float*)d_in[2];
    const float* bq   = (const float*)d_in[3];
    const float* Wk   = (const float*)d_in[4];
    const float* bk   = (const float*)d_in[5];
    const float* Wv   = (const float*)d_in[6];
    /* d_in[7] = bv: cancels in softmax */
    const float* Wo   = (const float*)d_in[8];
    const float* bo   = (const float*)d_in[9];

    float* o        = (float*)d_out;
    float* out_out  = o;
    float* attn_out = nullptr;
    float* mix_out  = nullptr;
    if (out_size >= B_ * D_ + B_ * TI_ + B_ * D_) {
        attn_out = o + B_ * D_;
        mix_out  = o + B_ * D_ + B_ * TI_;
    }

    cudaFuncSetAttribute(k_scores_mma, cudaFuncAttributeMaxDynamicSharedMemorySize, SMEM_SC);

    k_prep<<<256, 256>>>(Wk);
    k_query<<<B_, 512>>>(outp, Wq, bq, bk);
    k_scores_mma<<<dim3(NCHUNK, M_TOTAL / 128), 256, SMEM_SC>>>(ctx, Wv);
    k_softmax<<<B_, 512>>>(attn_out);
    k_mix<<<dim3(TSPLIT, B_), 256>>>(ctx);
    k_out<<<B_, 512>>>(outp, Wo, bo, out_out, mix_out);
}